// round 4
// baseline (speedup 1.0000x reference)
#include <cuda_runtime.h>
#include <cstdint>

typedef unsigned int u32;

#define EPSBN 1e-5f
#define C1 512
#define C2 128
#define C3 32
#define HW 784
#define PTOT (64*HW)   // 50176

// ---------------- device scratch ----------------
__device__ u32   g_pmn[1040], g_pmx[1040];   // per-block min/max partials (encoded)
__device__ u32   g_mm[8];                    // [6,7] = a2 min/max atomics
__device__ float g_qp[12];                   // [0..2]=a1 [3..5]=w1 [6..8]=w2  (mn,s,rcp)
__device__ u32   g_wq1_32[C2*C1/4];          // w1 u8 packed [co][128]
__device__ int   g_ws1[C2];                  // per-co w1 index sums
__device__ u32   g_wq2t[9*32*32];            // w2 u8 packed [tap*32+kg][co]
__device__ int   g_wts2[C3*9];               // per-(co,tap) w2 index sums
__device__ float g_a2[(size_t)PTOT*C2];      // relu(bn2(h)) fp32 NHWC (25.7MB)
__device__ u32   g_aq2[(size_t)PTOT*32];     // quantized a2 u8x4 NHWC (6.4MB)
__device__ int   g_rs2[PTOT];                // per-pixel a2 index sums

// ---------------- helpers ----------------
__device__ __forceinline__ u32 fenc(float f){
    u32 u = __float_as_uint(f);
    return (u & 0x80000000u) ? ~u : (u | 0x80000000u);
}
__device__ __forceinline__ float fdec(u32 e){
    return __uint_as_float((e & 0x80000000u) ? (e & 0x7fffffffu) : ~e);
}
__device__ __forceinline__ int qidx(float v, float mn, float s, float r){
    float t  = __fsub_rn(v, mn);
    float q0 = __fmul_rn(t, r);
    float q  = __fmaf_rn(__fmaf_rn(-s, q0, t), r, q0);
    int i = __float2int_rn(q);
    i = i < 0 ? 0 : i;
    return i > 255 ? 255 : i;
}
// u8 IMMA: D(16x8,s32) += A(16x32,u8,row) * B(32x8,u8,col)
__device__ __forceinline__ void imma(int* c, u32 a0, u32 a1, u32 a2, u32 a3, u32 b0, u32 b1){
    asm volatile("mma.sync.aligned.m16n8k32.row.col.s32.u8.u8.s32 "
                 "{%0,%1,%2,%3},{%4,%5,%6,%7},{%8,%9},{%0,%1,%2,%3};"
                 : "+r"(c[0]), "+r"(c[1]), "+r"(c[2]), "+r"(c[3])
                 : "r"(a0), "r"(a1), "r"(a2), "r"(a3), "r"(b0), "r"(b1));
}

// ---------------- K1: all min/max partials ----------------
__global__ void k_mm(const float* __restrict__ x, const float* __restrict__ g1,
                     const float* __restrict__ b1, const float* __restrict__ m1,
                     const float* __restrict__ v1, const float* __restrict__ w1,
                     const float* __restrict__ w2){
    __shared__ float sinv[C1], sbias[C1];
    __shared__ u32 wmin[8], wmax[8];
    int b = blockIdx.x, t = threadIdx.x;
    float lmin = 3.4e38f, lmax = -3.4e38f;
    if (b < 1024){
        for (int c = t; c < C1; c += 256){
            float iv = __fdiv_rn(g1[c], __fsqrt_rn(v1[c] + EPSBN));
            sinv[c]  = iv;
            sbias[c] = __fmaf_rn(-m1[c], iv, b1[c]);
        }
        __syncthreads();
        const float4* x4 = (const float4*)x;
        const int tot = 64*C1*HW/4;
        for (int i = b*256 + t; i < tot; i += 1024*256){
            int c = (i/196) & (C1-1);
            float iv = sinv[c], bb = sbias[c];
            float4 v = x4[i];
            float a0 = fmaxf(__fmaf_rn(v.x, iv, bb), 0.f);
            float a1 = fmaxf(__fmaf_rn(v.y, iv, bb), 0.f);
            float a2 = fmaxf(__fmaf_rn(v.z, iv, bb), 0.f);
            float a3 = fmaxf(__fmaf_rn(v.w, iv, bb), 0.f);
            lmax = fmaxf(lmax, fmaxf(fmaxf(a0,a1), fmaxf(a2,a3)));
            lmin = fminf(lmin, fminf(fminf(a0,a1), fminf(a2,a3)));
        }
    } else if (b < 1032){
        int s0 = (b-1024)*8192;
        for (int i = t; i < 8192; i += 256){
            float v = w1[s0+i];
            lmin = fminf(lmin, v); lmax = fmaxf(lmax, v);
        }
    } else {
        int s0 = (b-1032)*4608;
        for (int i = t; i < 4608; i += 256){
            float v = w2[s0+i];
            lmin = fminf(lmin, v); lmax = fmaxf(lmax, v);
        }
    }
    u32 emin = __reduce_min_sync(0xffffffffu, fenc(lmin));
    u32 emax = __reduce_max_sync(0xffffffffu, fenc(lmax));
    if ((t & 31) == 0){ wmin[t>>5] = emin; wmax[t>>5] = emax; }
    __syncthreads();
    if (t == 0){
        u32 mn = wmin[0], mx = wmax[0];
        for (int i = 1; i < 8; i++){ mn = min(mn, wmin[i]); mx = max(mx, wmax[i]); }
        g_pmn[b] = mn; g_pmx[b] = mx;
    }
}

// ---------------- K2: params + weight quantization ----------------
__global__ void k_prep(const float* __restrict__ w1, const float* __restrict__ w2){
    __shared__ int ss[9];
    __shared__ u32 smn[8], smx[8];
    int b = blockIdx.x, t = threadIdx.x;
    if (b < 128){
        u32 emn = g_pmn[1024], emx = g_pmx[1024];
        #pragma unroll
        for (int i = 1; i < 8; i++){ emn = min(emn, g_pmn[1024+i]); emx = max(emx, g_pmx[1024+i]); }
        float mn = fdec(emn), mx = fdec(emx);
        float s = fmaxf(__fdiv_rn(mx - mn, 255.0f), 1e-8f), r = __frcp_rn(s);
        int co = b;
        int lsum = 0;
        if (t < 128){
            u32 pack = 0;
            #pragma unroll
            for (int j = 0; j < 4; j++){
                int q = qidx(w1[co*C1 + 4*t + j], mn, s, r);
                pack |= (u32)q << (8*j);
                lsum += q;
            }
            g_wq1_32[co*128 + t] = pack;
        }
        lsum = __reduce_add_sync(0xffffffffu, lsum);
        if ((t & 31) == 0) ss[t>>5] = lsum;
        __syncthreads();
        if (t == 0){
            g_ws1[co] = ss[0] + ss[1] + ss[2] + ss[3];
            if (co == 0){ g_qp[3]=mn; g_qp[4]=s; g_qp[5]=r; }
        }
    } else if (b < 160){
        int co = b - 128;
        u32 emn = g_pmn[1032], emx = g_pmx[1032];
        #pragma unroll
        for (int i = 1; i < 8; i++){ emn = min(emn, g_pmn[1032+i]); emx = max(emx, g_pmx[1032+i]); }
        float mn = fdec(emn), mx = fdec(emx);
        float s = fmaxf(__fdiv_rn(mx - mn, 255.0f), 1e-8f), r = __frcp_rn(s);
        if (t < 9) ss[t] = 0;
        __syncthreads();
        for (int f = t; f < 288; f += 256){
            int tap = f / 32, kg = f % 32;
            u32 pack = 0; int psum = 0;
            #pragma unroll
            for (int j = 0; j < 4; j++){
                int ci = kg*4 + j;
                int q = qidx(w2[co*1152 + ci*9 + tap], mn, s, r);
                pack |= (u32)q << (8*j);
                psum += q;
            }
            g_wq2t[(tap*32 + kg)*32 + co] = pack;
            atomicAdd(&ss[tap], psum);
        }
        __syncthreads();
        if (t < 9) g_wts2[co*9 + t] = ss[t];
        if (t == 0 && co == 0){ g_qp[6]=mn; g_qp[7]=s; g_qp[8]=r; }
    } else {
        u32 emn = 0xFFFFFFFFu, emx = 0u;
        for (int i = t; i < 1024; i += 256){ emn = min(emn, g_pmn[i]); emx = max(emx, g_pmx[i]); }
        emn = __reduce_min_sync(0xffffffffu, emn);
        emx = __reduce_max_sync(0xffffffffu, emx);
        if ((t & 31) == 0){ smn[t>>5] = emn; smx[t>>5] = emx; }
        __syncthreads();
        if (t == 0){
            u32 mn2 = smn[0], mx2 = smx[0];
            for (int i = 1; i < 8; i++){ mn2 = min(mn2, smn[i]); mx2 = max(mx2, smx[i]); }
            float mn = fdec(mn2), mx = fdec(mx2);
            float s = fmaxf(__fdiv_rn(mx - mn, 255.0f), 1e-8f);
            g_qp[0] = mn; g_qp[1] = s; g_qp[2] = __frcp_rn(s);
            g_mm[6] = 0xFFFFFFFFu; g_mm[7] = 0u;
        }
    }
}

// ---------------- K3: conv1 via IMMA (mma.sync u8) ----------------
// dyn smem (u32 units): As[128*132] | Ws[128*132] | params
#define AS_U32   (128*132)
#define SP_U32   (2*AS_U32)
#define DYN_SMEM (SP_U32*4 + 6400)

__global__ __launch_bounds__(256) void k_conv1(
    const float* __restrict__ x,
    const float* __restrict__ g1, const float* __restrict__ b1,
    const float* __restrict__ m1, const float* __restrict__ v1,
    const float* __restrict__ g2, const float* __restrict__ b2,
    const float* __restrict__ m2, const float* __restrict__ v2)
{
    extern __shared__ __align__(16) u32 sm[];
    u32* As = sm;
    u32* Ws = sm + AS_U32;
    float* inv1 = (float*)(sm + SP_U32);
    float* bia1 = inv1 + 512;
    float* inv2 = bia1 + 512;
    float* bia2 = inv2 + 128;
    int*   ws_s = (int*)(bia2 + 128);
    int*   rs_s = ws_s + 128;
    u32*   red  = (u32*)(rs_s + 128);

    int tid = threadIdx.x, wid = tid >> 5, lane = tid & 31;
    int g = lane >> 2, tg = lane & 3;
    int p0 = blockIdx.x * 128;

    for (int c = tid; c < C1; c += 256){
        float iv = __fdiv_rn(g1[c], __fsqrt_rn(v1[c] + EPSBN));
        inv1[c] = iv; bia1[c] = __fmaf_rn(-m1[c], iv, b1[c]);
    }
    if (tid < 128){
        float iv = __fdiv_rn(g2[tid], __fsqrt_rn(v2[tid] + EPSBN));
        inv2[tid] = iv; bia2[tid] = __fmaf_rn(-m2[tid], iv, b2[tid]);
        ws_s[tid] = g_ws1[tid];
        rs_s[tid] = 0;
    }
    // load weights to smem
    #pragma unroll
    for (int it = 0; it < 64; it++){
        int f = it*256 + tid;
        Ws[(f>>7)*132 + (f&127)] = g_wq1_32[f];
    }
    __syncthreads();

    float mnA = g_qp[0], sA = g_qp[1], rA = g_qp[2];

    // ---- build quantized u8 activation tile A [128px][512ci] ----
    {
        int px = tid & 127, half = tid >> 7;
        int p = p0 + px;
        u32 base = (u32)((p/HW)*(C1*HW) + (p%HW));
        int lsum = 0;
        #pragma unroll 4
        for (int m = 0; m < 64; m++){
            int ci = half*256 + 4*m;
            u32 pack = 0;
            #pragma unroll
            for (int j = 0; j < 4; j++){
                float xv = x[base + (u32)(ci+j)*HW];
                float a = fmaxf(__fmaf_rn(xv, inv1[ci+j], bia1[ci+j]), 0.f);
                int q = qidx(a, mnA, sA, rA);
                pack |= (u32)q << (8*j);
                lsum += q;
            }
            As[px*132 + half*64 + m] = pack;
        }
        atomicAdd(&rs_s[px], lsum);
    }
    __syncthreads();

    // ---- IMMA mainloop: warp computes 32px x 64co ----
    int r0 = (wid >> 1) * 32;
    int c0 = (wid & 1) * 64;
    int acc[2][8][4];
    #pragma unroll
    for (int rt = 0; rt < 2; rt++)
        #pragma unroll
        for (int ct = 0; ct < 8; ct++)
            #pragma unroll
            for (int d = 0; d < 4; d++) acc[rt][ct][d] = 0;

    #pragma unroll 4
    for (int kk = 0; kk < 16; kk++){
        int kg0 = kk*8;
        u32 a[2][4];
        #pragma unroll
        for (int rt = 0; rt < 2; rt++){
            int row = r0 + rt*16;
            a[rt][0] = As[(row + g)*132     + kg0 + tg];
            a[rt][1] = As[(row + 8 + g)*132 + kg0 + tg];
            a[rt][2] = As[(row + g)*132     + kg0 + 4 + tg];
            a[rt][3] = As[(row + 8 + g)*132 + kg0 + 4 + tg];
        }
        #pragma unroll
        for (int ct = 0; ct < 8; ct++){
            int co = c0 + ct*8 + g;
            u32 b0 = Ws[co*132 + kg0 + tg];
            u32 b1 = Ws[co*132 + kg0 + 4 + tg];
            imma(acc[0][ct], a[0][0], a[0][1], a[0][2], a[0][3], b0, b1);
            imma(acc[1][ct], a[1][0], a[1][1], a[1][2], a[1][3], b0, b1);
        }
    }
    __syncthreads();   // done reading As; reuse as fp32 staging

    // ---- epilogue: reconstruct, bn2+relu, minmax, stage, store ----
    float mnW = g_qp[3], sW = g_qp[4];
    float SS = sA * sW;
    float c0f = 512.0f * mnA * mnW;
    float* fo = (float*)As;
    float lmin = 3.4e38f, lmax = -3.4e38f;
    #pragma unroll
    for (int rt = 0; rt < 2; rt++){
        #pragma unroll
        for (int dd = 0; dd < 2; dd++){
            int px = r0 + rt*16 + g + dd*8;
            float t1 = __fmaf_rn(sA*mnW, (float)rs_s[px], c0f);
            #pragma unroll
            for (int ct = 0; ct < 8; ct++){
                #pragma unroll
                for (int e = 0; e < 2; e++){
                    int co = c0 + ct*8 + 2*tg + e;
                    float h = __fmaf_rn(SS, (float)acc[rt][ct][dd*2+e],
                              __fmaf_rn(mnA*sW, (float)ws_s[co], t1));
                    float a2 = fmaxf(__fmaf_rn(h, inv2[co], bia2[co]), 0.f);
                    fo[px*132 + co] = a2;
                    lmin = fminf(lmin, a2); lmax = fmaxf(lmax, a2);
                }
            }
        }
    }
    u32 emin = __reduce_min_sync(0xffffffffu, fenc(lmin));
    u32 emax = __reduce_max_sync(0xffffffffu, fenc(lmax));
    if (lane == 0){ red[wid] = emin; red[8+wid] = emax; }
    __syncthreads();
    if (tid == 0){
        u32 mn = red[0], mx = red[8];
        for (int i = 1; i < 8; i++){ mn = min(mn, red[i]); mx = max(mx, red[8+i]); }
        atomicMin(&g_mm[6], mn); atomicMax(&g_mm[7], mx);
    }
    #pragma unroll
    for (int it = 0; it < 16; it++){
        int f = it*256 + tid;
        int pxi = f >> 5, j = f & 31;
        float4 v = *(float4*)&fo[pxi*132 + j*4];
        *(float4*)&g_a2[(size_t)(p0 + pxi)*C2 + j*4] = v;
    }
}

// ---------------- K4: quantize a2 ----------------
__global__ void k_qa2(){
    int warp = threadIdx.x >> 5, lane = threadIdx.x & 31;
    int p = blockIdx.x*8 + warp;
    float mn = fdec(g_mm[6]), mx = fdec(g_mm[7]);
    float s = fmaxf(__fdiv_rn(mx - mn, 255.0f), 1e-8f), r = __frcp_rn(s);
    const float4* a4 = (const float4*)&g_a2[(size_t)p*C2];
    float4 v = a4[lane];
    int q0 = qidx(v.x, mn, s, r);
    int q1 = qidx(v.y, mn, s, r);
    int q2 = qidx(v.z, mn, s, r);
    int q3 = qidx(v.w, mn, s, r);
    g_aq2[(size_t)p*32 + lane] = (u32)q0 | ((u32)q1<<8) | ((u32)q2<<16) | ((u32)q3<<24);
    int sum = __reduce_add_sync(0xffffffffu, q0+q1+q2+q3);
    if (lane == 0) g_rs2[p] = sum;
}

// ---------------- K5: 3x3 conv via dp4a ----------------
__global__ __launch_bounds__(128) void k_conv2(float* __restrict__ out){
    __shared__ u32 w_s[9*32*32];
    __shared__ u32 a_t[3*30*32];
    __shared__ int rs_s[3*30];
    int tid = threadIdx.x;
    int b = blockIdx.x;
    int n = b / 28, h = b % 28;

    for (int f = tid; f < 9*32*32; f += 128) w_s[f] = g_wq2t[f];
    for (int f = tid; f < 3*30*32; f += 128) a_t[f] = 0;
    if (tid < 90) rs_s[tid] = 0;
    __syncthreads();
    for (int f = tid; f < 3*28*32; f += 128){
        int rr = f / (28*32); int rem = f - rr*28*32;
        int col = rem >> 5, k = rem & 31;
        int gh = h + rr - 1;
        if ((unsigned)gh < 28u)
            a_t[(rr*30 + col + 1)*32 + k] = g_aq2[(size_t)(n*HW + gh*28 + col)*32 + k];
    }
    if (tid < 84){
        int rr = tid / 28, col = tid % 28;
        int gh = h + rr - 1;
        if ((unsigned)gh < 28u) rs_s[rr*30 + col + 1] = g_rs2[n*HW + gh*28 + col];
    }
    __syncthreads();

    int co = tid & 31, pg = tid >> 5;
    int pbase = pg * 7;
    u32 acc[7] = {};
    #pragma unroll 4
    for (int k = 0; k < 32; k++){
        u32 wv[9], av[3][9];
        #pragma unroll
        for (int t = 0; t < 9; t++) wv[t] = w_s[(t*32 + k)*32 + co];
        #pragma unroll
        for (int rr = 0; rr < 3; rr++)
            #pragma unroll
            for (int c = 0; c < 9; c++)
                av[rr][c] = a_t[(rr*30 + pbase + c)*32 + k];
        #pragma unroll
        for (int i = 0; i < 7; i++)
            #pragma unroll
            for (int rr = 0; rr < 3; rr++)
                #pragma unroll
                for (int dw = 0; dw < 3; dw++)
                    acc[i] = __dp4a(av[rr][i+dw], wv[rr*3+dw], acc[i]);
    }

    float mnA2 = fdec(g_mm[6]), mxA2 = fdec(g_mm[7]);
    float sA2 = fmaxf(__fdiv_rn(mxA2 - mnA2, 255.0f), 1e-8f);
    float mnW = g_qp[6], sW = g_qp[7];
    int rowv = 0;
    #pragma unroll
    for (int rr = 0; rr < 3; rr++) rowv += ((unsigned)(h + rr - 1) < 28u);
    int wts[9];
    #pragma unroll
    for (int t = 0; t < 9; t++) wts[t] = g_wts2[co*9 + t];
    float* obase = out + ((size_t)n*32 + co)*HW + h*28;
    #pragma unroll
    for (int i = 0; i < 7; i++){
        int px = pbase + i;
        int rssum = 0;
        #pragma unroll
        for (int rr = 0; rr < 3; rr++)
            #pragma unroll
            for (int dw = 0; dw < 3; dw++)
                rssum += rs_s[rr*30 + px + dw];
        int wvsum = 0, nvc = 0;
        #pragma unroll
        for (int dw = 0; dw < 3; dw++){
            if ((unsigned)(px + dw - 1) < 28u){
                nvc++;
                #pragma unroll
                for (int rr = 0; rr < 3; rr++)
                    if ((unsigned)(h + rr - 1) < 28u) wvsum += wts[rr*3 + dw];
            }
        }
        int nv = rowv * nvc;
        float o = sA2*sW*(float)(int)acc[i] + sA2*mnW*(float)rssum
                + mnA2*sW*(float)wvsum + mnA2*mnW*128.0f*(float)nv;
        obase[px] = o;
    }
}

extern "C" void kernel_launch(void* const* d_in, const int* in_sizes, int n_in,
                              void* d_out, int out_size){
    const float* x  = (const float*)d_in[0];
    const float* g1 = (const float*)d_in[1];
    const float* b1 = (const float*)d_in[2];
    const float* m1 = (const float*)d_in[3];
    const float* v1 = (const float*)d_in[4];
    const float* w1 = (const float*)d_in[5];
    const float* g2 = (const float*)d_in[6];
    const float* b2 = (const float*)d_in[7];
    const float* m2 = (const float*)d_in[8];
    const float* v2 = (const float*)d_in[9];
    const float* w2 = (const float*)d_in[10];
    float* out = (float*)d_out;

    cudaFuncSetAttribute(k_conv1, cudaFuncAttributeMaxDynamicSharedMemorySize, DYN_SMEM);

    k_mm   <<<1040, 256>>>(x, g1, b1, m1, v1, w1, w2);
    k_prep <<<161, 256>>>(w1, w2);
    k_conv1<<<392, 256, DYN_SMEM>>>(x, g1, b1, m1, v1, g2, b2, m2, v2);
    k_qa2  <<<6272, 256>>>();
    k_conv2<<<1792, 128>>>(out);
}

// round 5
// speedup vs baseline: 1.3354x; 1.3354x over previous
#include <cuda_runtime.h>
#include <cstdint>

typedef unsigned int u32;

#define EPSBN 1e-5f
#define C1 512
#define C2 128
#define C3 32
#define HW 784
#define PTOT (64*HW)   // 50176

// ---------------- device scratch ----------------
__device__ u32   g_pmn[1040], g_pmx[1040];   // per-block min/max partials (encoded)
__device__ u32   g_mm[8];                    // [6,7] = a2 min/max atomics
__device__ float g_qp[12];                   // [0..2]=a1 [3..5]=w1 [6..8]=w2  (mn,s,rcp)
__device__ u32   g_wq1_32[C2*C1/4];          // w1 u8 packed [co][128]
__device__ int   g_ws1[C2];                  // per-co w1 index sums
__device__ u32   g_wq2c[C3*288];             // w2 u8 packed [co][tap*32+kg]  (co-major)
__device__ int   g_wts2[C3*9];               // per-(co,tap) w2 index sums
__device__ float g_a2[(size_t)PTOT*C2];      // relu(bn2(h)) fp32 NHWC (25.7MB)
__device__ u32   g_aq2[(size_t)PTOT*32];     // quantized a2 u8x4 NHWC (6.4MB)
__device__ int   g_rs2[PTOT];                // per-pixel a2 index sums

// ---------------- helpers ----------------
__device__ __forceinline__ u32 fenc(float f){
    u32 u = __float_as_uint(f);
    return (u & 0x80000000u) ? ~u : (u | 0x80000000u);
}
__device__ __forceinline__ float fdec(u32 e){
    return __uint_as_float((e & 0x80000000u) ? (e & 0x7fffffffu) : ~e);
}
__device__ __forceinline__ int qidx(float v, float mn, float s, float r){
    float t  = __fsub_rn(v, mn);
    float q0 = __fmul_rn(t, r);
    float q  = __fmaf_rn(__fmaf_rn(-s, q0, t), r, q0);
    int i = __float2int_rn(q);
    i = i < 0 ? 0 : i;
    return i > 255 ? 255 : i;
}
// u8 IMMA: D(16x8,s32) += A(16x32,u8,row) * B(32x8,u8,col)
__device__ __forceinline__ void imma(int* c, u32 a0, u32 a1, u32 a2, u32 a3, u32 b0, u32 b1){
    asm volatile("mma.sync.aligned.m16n8k32.row.col.s32.u8.u8.s32 "
                 "{%0,%1,%2,%3},{%4,%5,%6,%7},{%8,%9},{%0,%1,%2,%3};"
                 : "+r"(c[0]), "+r"(c[1]), "+r"(c[2]), "+r"(c[3])
                 : "r"(a0), "r"(a1), "r"(a2), "r"(a3), "r"(b0), "r"(b1));
}

// ---------------- K1: all min/max partials ----------------
__global__ void k_mm(const float* __restrict__ x, const float* __restrict__ g1,
                     const float* __restrict__ b1, const float* __restrict__ m1,
                     const float* __restrict__ v1, const float* __restrict__ w1,
                     const float* __restrict__ w2){
    __shared__ float sinv[C1], sbias[C1];
    __shared__ u32 wmin[8], wmax[8];
    int b = blockIdx.x, t = threadIdx.x;
    float lmin = 3.4e38f, lmax = -3.4e38f;
    if (b < 1024){
        for (int c = t; c < C1; c += 256){
            float iv = __fdiv_rn(g1[c], __fsqrt_rn(v1[c] + EPSBN));
            sinv[c]  = iv;
            sbias[c] = __fmaf_rn(-m1[c], iv, b1[c]);
        }
        __syncthreads();
        const float4* x4 = (const float4*)x;
        const int tot = 64*C1*HW/4;
        const int step = 1024*256;
        int i = b*256 + t;
        for (; i + step < tot; i += 2*step){
            int c1i = (i/196) & (C1-1);
            int c2i = ((i+step)/196) & (C1-1);
            float4 u = x4[i];
            float4 w = x4[i+step];
            float iv1 = sinv[c1i], bb1 = sbias[c1i];
            float iv2 = sinv[c2i], bb2 = sbias[c2i];
            float a0 = fmaxf(__fmaf_rn(u.x, iv1, bb1), 0.f);
            float a1 = fmaxf(__fmaf_rn(u.y, iv1, bb1), 0.f);
            float a2 = fmaxf(__fmaf_rn(u.z, iv1, bb1), 0.f);
            float a3 = fmaxf(__fmaf_rn(u.w, iv1, bb1), 0.f);
            float b0 = fmaxf(__fmaf_rn(w.x, iv2, bb2), 0.f);
            float b1_ = fmaxf(__fmaf_rn(w.y, iv2, bb2), 0.f);
            float b2 = fmaxf(__fmaf_rn(w.z, iv2, bb2), 0.f);
            float b3 = fmaxf(__fmaf_rn(w.w, iv2, bb2), 0.f);
            lmax = fmaxf(lmax, fmaxf(fmaxf(fmaxf(a0,a1), fmaxf(a2,a3)),
                                     fmaxf(fmaxf(b0,b1_), fmaxf(b2,b3))));
            lmin = fminf(lmin, fminf(fminf(fminf(a0,a1), fminf(a2,a3)),
                                     fminf(fminf(b0,b1_), fminf(b2,b3))));
        }
        if (i < tot){
            int c = (i/196) & (C1-1);
            float iv = sinv[c], bb = sbias[c];
            float4 v = x4[i];
            float a0 = fmaxf(__fmaf_rn(v.x, iv, bb), 0.f);
            float a1 = fmaxf(__fmaf_rn(v.y, iv, bb), 0.f);
            float a2 = fmaxf(__fmaf_rn(v.z, iv, bb), 0.f);
            float a3 = fmaxf(__fmaf_rn(v.w, iv, bb), 0.f);
            lmax = fmaxf(lmax, fmaxf(fmaxf(a0,a1), fmaxf(a2,a3)));
            lmin = fminf(lmin, fminf(fminf(a0,a1), fminf(a2,a3)));
        }
    } else if (b < 1032){
        int s0 = (b-1024)*8192;
        for (int i = t; i < 8192; i += 256){
            float v = w1[s0+i];
            lmin = fminf(lmin, v); lmax = fmaxf(lmax, v);
        }
    } else {
        int s0 = (b-1032)*4608;
        for (int i = t; i < 4608; i += 256){
            float v = w2[s0+i];
            lmin = fminf(lmin, v); lmax = fmaxf(lmax, v);
        }
    }
    u32 emin = __reduce_min_sync(0xffffffffu, fenc(lmin));
    u32 emax = __reduce_max_sync(0xffffffffu, fenc(lmax));
    if ((t & 31) == 0){ wmin[t>>5] = emin; wmax[t>>5] = emax; }
    __syncthreads();
    if (t == 0){
        u32 mn = wmin[0], mx = wmax[0];
        for (int i = 1; i < 8; i++){ mn = min(mn, wmin[i]); mx = max(mx, wmax[i]); }
        g_pmn[b] = mn; g_pmx[b] = mx;
    }
}

// ---------------- K2: params + weight quantization ----------------
__global__ void k_prep(const float* __restrict__ w1, const float* __restrict__ w2){
    __shared__ int ss[9];
    __shared__ u32 smn[8], smx[8];
    int b = blockIdx.x, t = threadIdx.x;
    if (b < 128){
        u32 emn = g_pmn[1024], emx = g_pmx[1024];
        #pragma unroll
        for (int i = 1; i < 8; i++){ emn = min(emn, g_pmn[1024+i]); emx = max(emx, g_pmx[1024+i]); }
        float mn = fdec(emn), mx = fdec(emx);
        float s = fmaxf(__fdiv_rn(mx - mn, 255.0f), 1e-8f), r = __frcp_rn(s);
        int co = b;
        int lsum = 0;
        if (t < 128){
            u32 pack = 0;
            #pragma unroll
            for (int j = 0; j < 4; j++){
                int q = qidx(w1[co*C1 + 4*t + j], mn, s, r);
                pack |= (u32)q << (8*j);
                lsum += q;
            }
            g_wq1_32[co*128 + t] = pack;
        }
        lsum = __reduce_add_sync(0xffffffffu, lsum);
        if ((t & 31) == 0) ss[t>>5] = lsum;
        __syncthreads();
        if (t == 0){
            g_ws1[co] = ss[0] + ss[1] + ss[2] + ss[3];
            if (co == 0){ g_qp[3]=mn; g_qp[4]=s; g_qp[5]=r; }
        }
    } else if (b < 160){
        int co = b - 128;
        u32 emn = g_pmn[1032], emx = g_pmx[1032];
        #pragma unroll
        for (int i = 1; i < 8; i++){ emn = min(emn, g_pmn[1032+i]); emx = max(emx, g_pmx[1032+i]); }
        float mn = fdec(emn), mx = fdec(emx);
        float s = fmaxf(__fdiv_rn(mx - mn, 255.0f), 1e-8f), r = __frcp_rn(s);
        if (t < 9) ss[t] = 0;
        __syncthreads();
        for (int f = t; f < 288; f += 256){
            int tap = f >> 5, kg = f & 31;
            u32 pack = 0; int psum = 0;
            #pragma unroll
            for (int j = 0; j < 4; j++){
                int ci = kg*4 + j;
                int q = qidx(w2[co*1152 + ci*9 + tap], mn, s, r);
                pack |= (u32)q << (8*j);
                psum += q;
            }
            g_wq2c[co*288 + f] = pack;
            atomicAdd(&ss[tap], psum);
        }
        __syncthreads();
        if (t < 9) g_wts2[co*9 + t] = ss[t];
        if (t == 0 && co == 0){ g_qp[6]=mn; g_qp[7]=s; g_qp[8]=r; }
    } else {
        u32 emn = 0xFFFFFFFFu, emx = 0u;
        for (int i = t; i < 1024; i += 256){ emn = min(emn, g_pmn[i]); emx = max(emx, g_pmx[i]); }
        emn = __reduce_min_sync(0xffffffffu, emn);
        emx = __reduce_max_sync(0xffffffffu, emx);
        if ((t & 31) == 0){ smn[t>>5] = emn; smx[t>>5] = emx; }
        __syncthreads();
        if (t == 0){
            u32 mn2 = smn[0], mx2 = smx[0];
            for (int i = 1; i < 8; i++){ mn2 = min(mn2, smn[i]); mx2 = max(mx2, smx[i]); }
            float mn = fdec(mn2), mx = fdec(mx2);
            float s = fmaxf(__fdiv_rn(mx - mn, 255.0f), 1e-8f);
            g_qp[0] = mn; g_qp[1] = s; g_qp[2] = __frcp_rn(s);
            g_mm[6] = 0xFFFFFFFFu; g_mm[7] = 0u;
        }
    }
}

// ---------------- K3: conv1 via IMMA, 64px tiles, 2 CTA/SM ----------------
#define AS_U32   (64*132)         // 8448
#define WS_U32   (128*132)        // 16896
#define SP_U32   (AS_U32+WS_U32)  // 25344
#define DYN_SMEM (SP_U32*4 + 6400)

__global__ __launch_bounds__(256,2) void k_conv1(
    const float* __restrict__ x,
    const float* __restrict__ g1, const float* __restrict__ b1,
    const float* __restrict__ m1, const float* __restrict__ v1,
    const float* __restrict__ g2, const float* __restrict__ b2,
    const float* __restrict__ m2, const float* __restrict__ v2)
{
    extern __shared__ __align__(16) u32 sm[];
    u32* As = sm;
    u32* Ws = sm + AS_U32;
    float* inv1 = (float*)(sm + SP_U32);
    float* bia1 = inv1 + 512;
    float* inv2 = bia1 + 512;
    float* bia2 = inv2 + 128;
    int*   ws_s = (int*)(bia2 + 128);
    int*   rs_s = ws_s + 128;
    u32*   red  = (u32*)(rs_s + 64);

    int tid = threadIdx.x, wid = tid >> 5, lane = tid & 31;
    int g = lane >> 2, tg = lane & 3;
    int p0 = blockIdx.x * 64;

    for (int c = tid; c < C1; c += 256){
        float iv = __fdiv_rn(g1[c], __fsqrt_rn(v1[c] + EPSBN));
        inv1[c] = iv; bia1[c] = __fmaf_rn(-m1[c], iv, b1[c]);
    }
    if (tid < 128){
        float iv = __fdiv_rn(g2[tid], __fsqrt_rn(v2[tid] + EPSBN));
        inv2[tid] = iv; bia2[tid] = __fmaf_rn(-m2[tid], iv, b2[tid]);
        ws_s[tid] = g_ws1[tid];
    }
    if (tid < 64) rs_s[tid] = 0;
    // load all weights (128co x 128 words)
    #pragma unroll
    for (int it = 0; it < 64; it++){
        int f = it*256 + tid;
        Ws[(f>>7)*132 + (f&127)] = g_wq1_32[f];
    }
    __syncthreads();

    float mnA = g_qp[0], sA = g_qp[1], rA = g_qp[2];

    // ---- build quantized u8 activation tile A [64px][512ci] ----
    {
        int px = tid & 63, q4 = tid >> 6;
        int p = p0 + px;
        u32 base = (u32)((p/HW)*(C1*HW) + (p%HW));
        int ci0 = q4 * 128;
        int lsum = 0;
        #pragma unroll 4
        for (int m = 0; m < 32; m++){
            int ci = ci0 + 4*m;
            u32 pack = 0;
            #pragma unroll
            for (int j = 0; j < 4; j++){
                float xv = x[base + (u32)(ci+j)*HW];
                float a = fmaxf(__fmaf_rn(xv, inv1[ci+j], bia1[ci+j]), 0.f);
                int q = qidx(a, mnA, sA, rA);
                pack |= (u32)q << (8*j);
                lsum += q;
            }
            As[px*132 + q4*32 + m] = pack;
        }
        atomicAdd(&rs_s[px], lsum);
    }
    __syncthreads();

    // ---- IMMA mainloop: warp computes 16px x 64co ----
    int r0 = (wid >> 1) * 16;
    int c0 = (wid & 1) * 64;
    int acc[8][4];
    #pragma unroll
    for (int ct = 0; ct < 8; ct++)
        #pragma unroll
        for (int d = 0; d < 4; d++) acc[ct][d] = 0;

    #pragma unroll 4
    for (int kk = 0; kk < 16; kk++){
        int kg0 = kk*8;
        u32 a0 = As[(r0 + g)*132     + kg0 + tg];
        u32 a1 = As[(r0 + 8 + g)*132 + kg0 + tg];
        u32 a2 = As[(r0 + g)*132     + kg0 + 4 + tg];
        u32 a3 = As[(r0 + 8 + g)*132 + kg0 + 4 + tg];
        #pragma unroll
        for (int ct = 0; ct < 8; ct++){
            int co = c0 + ct*8 + g;
            u32 b0 = Ws[co*132 + kg0 + tg];
            u32 b1 = Ws[co*132 + kg0 + 4 + tg];
            imma(acc[ct], a0, a1, a2, a3, b0, b1);
        }
    }
    __syncthreads();   // done reading As; reuse as fp32 staging

    // ---- epilogue ----
    float mnW = g_qp[3], sW = g_qp[4];
    float SS = sA * sW;
    float c0f = 512.0f * mnA * mnW;
    float* fo = (float*)As;
    float lmin = 3.4e38f, lmax = -3.4e38f;
    #pragma unroll
    for (int hh = 0; hh < 2; hh++){
        int px = r0 + hh*8 + g;
        float t1 = __fmaf_rn(sA*mnW, (float)rs_s[px], c0f);
        #pragma unroll
        for (int ct = 0; ct < 8; ct++){
            #pragma unroll
            for (int e = 0; e < 2; e++){
                int co = c0 + ct*8 + 2*tg + e;
                float h = __fmaf_rn(SS, (float)acc[ct][hh*2+e],
                          __fmaf_rn(mnA*sW, (float)ws_s[co], t1));
                float a2v = fmaxf(__fmaf_rn(h, inv2[co], bia2[co]), 0.f);
                fo[px*132 + co] = a2v;
                lmin = fminf(lmin, a2v); lmax = fmaxf(lmax, a2v);
            }
        }
    }
    u32 emin = __reduce_min_sync(0xffffffffu, fenc(lmin));
    u32 emax = __reduce_max_sync(0xffffffffu, fenc(lmax));
    if (lane == 0){ red[wid] = emin; red[8+wid] = emax; }
    __syncthreads();
    if (tid == 0){
        u32 mn = red[0], mx = red[8];
        for (int i = 1; i < 8; i++){ mn = min(mn, red[i]); mx = max(mx, red[8+i]); }
        atomicMin(&g_mm[6], mn); atomicMax(&g_mm[7], mx);
    }
    #pragma unroll
    for (int it = 0; it < 8; it++){
        int f = it*256 + tid;
        int pxi = f >> 5, j = f & 31;
        float4 v = *(float4*)&fo[pxi*132 + j*4];
        *(float4*)&g_a2[(size_t)(p0 + pxi)*C2 + j*4] = v;
    }
}

// ---------------- K4: quantize a2 ----------------
__global__ void k_qa2(){
    int warp = threadIdx.x >> 5, lane = threadIdx.x & 31;
    int p = blockIdx.x*8 + warp;
    float mn = fdec(g_mm[6]), mx = fdec(g_mm[7]);
    float s = fmaxf(__fdiv_rn(mx - mn, 255.0f), 1e-8f), r = __frcp_rn(s);
    const float4* a4 = (const float4*)&g_a2[(size_t)p*C2];
    float4 v = a4[lane];
    int q0 = qidx(v.x, mn, s, r);
    int q1 = qidx(v.y, mn, s, r);
    int q2 = qidx(v.z, mn, s, r);
    int q3 = qidx(v.w, mn, s, r);
    g_aq2[(size_t)p*32 + lane] = (u32)q0 | ((u32)q1<<8) | ((u32)q2<<16) | ((u32)q3<<24);
    int sum = __reduce_add_sync(0xffffffffu, q0+q1+q2+q3);
    if (lane == 0) g_rs2[p] = sum;
}

// ---------------- K5: 3x3 conv via IMMA ----------------
// K = 1152 ordered tap-major: word index = tap*32 + kg
__global__ __launch_bounds__(128) void k_conv2(float* __restrict__ out){
    __shared__ u32 Ws[32*292];      // [co][288 words], stride 292 (conflict-free)
    __shared__ u32 a_t[3*30*36];    // [row][col(halo)][32 words], stride 36
    __shared__ int   rs_s[3*30];
    __shared__ float rsum_p[28];
    __shared__ float wvL[32], wvM[32], wvR[32];

    int tid = threadIdx.x;
    int b = blockIdx.x;
    int n = b / 28, h = b % 28;
    int wid = tid >> 5, lane = tid & 31;
    int g = lane >> 2, tg = lane & 3;

    // load weights [co][288] coalesced, into padded rows
    for (int f = tid; f < 9216; f += 128){
        int co = f / 288, k = f - co*288;
        Ws[co*292 + k] = g_wq2c[f];
    }
    // zero activation tile (halo cols included)
    for (int f = tid; f < 3*30*36; f += 128) a_t[f] = 0;
    if (tid < 90) rs_s[tid] = 0;
    __syncthreads();
    // fill 3 input rows with halo offset +1
    for (int f = tid; f < 3*28*32; f += 128){
        int rr = f / (28*32); int rem = f - rr*28*32;
        int col = rem >> 5, k = rem & 31;
        int gh = h + rr - 1;
        if ((unsigned)gh < 28u)
            a_t[(rr*30 + col + 1)*36 + k] = g_aq2[(size_t)(n*HW + gh*28 + col)*32 + k];
    }
    if (tid < 84){
        int rr = tid / 28, col = tid % 28;
        int gh = h + rr - 1;
        if ((unsigned)gh < 28u) rs_s[rr*30 + col + 1] = g_rs2[n*HW + gh*28 + col];
    }
    __syncthreads();

    // per-pixel 3x3 window sums of activation indices
    if (tid < 28){
        int s = 0;
        #pragma unroll
        for (int rr = 0; rr < 3; rr++)
            #pragma unroll
            for (int dw = 0; dw < 3; dw++)
                s += rs_s[rr*30 + tid + dw];
        rsum_p[tid] = (float)s;
    }
    // per-co weight-sum classes (L: px=0 excludes dw0; R: px=27 excludes dw2)
    if (tid < 32){
        int co = tid;
        float m = 0.f, l = 0.f, r_ = 0.f;
        #pragma unroll
        for (int rr = 0; rr < 3; rr++){
            if ((unsigned)(h + rr - 1) < 28u){
                float w0 = (float)g_wts2[co*9 + rr*3 + 0];
                float w1 = (float)g_wts2[co*9 + rr*3 + 1];
                float w2 = (float)g_wts2[co*9 + rr*3 + 2];
                m  += w0 + w1 + w2;
                l  += w1 + w2;
                r_ += w0 + w1;
            }
        }
        wvM[co] = m; wvL[co] = l; wvR[co] = r_;
    }
    __syncthreads();

    // ---- IMMA: warp w handles co block w*8, M = 32 (px 0..27 + pad) ----
    int acc[2][4];
    #pragma unroll
    for (int i = 0; i < 2; i++)
        #pragma unroll
        for (int d = 0; d < 4; d++) acc[i][d] = 0;

    #pragma unroll
    for (int s = 0; s < 36; s++){
        int tap = s >> 2, chunk = s & 3;
        int rr = tap / 3, dw = tap - rr*3;
        int w0 = chunk*8 + tg;
        u32 b0 = Ws[(wid*8 + g)*292 + s*8 + tg];
        u32 b1 = Ws[(wid*8 + g)*292 + s*8 + 4 + tg];
        int rbase = rr*30 + dw;
        u32 a0 = a_t[(rbase + g)*36      + w0];
        u32 a1 = a_t[(rbase + 8 + g)*36  + w0];
        u32 a2 = a_t[(rbase + g)*36      + w0 + 4];
        u32 a3 = a_t[(rbase + 8 + g)*36  + w0 + 4];
        imma(acc[0], a0, a1, a2, a3, b0, b1);
        u32 c0 = a_t[(rbase + 16 + g)*36 + w0];
        u32 c1 = a_t[(rbase + 24 + g)*36 + w0];
        u32 c2 = a_t[(rbase + 16 + g)*36 + w0 + 4];
        u32 c3 = a_t[(rbase + 24 + g)*36 + w0 + 4];
        imma(acc[1], c0, c1, c2, c3, b0, b1);
    }

    // ---- epilogue ----
    float mnA2 = fdec(g_mm[6]), mxA2 = fdec(g_mm[7]);
    float sA2 = fmaxf(__fdiv_rn(mxA2 - mnA2, 255.0f), 1e-8f);
    float mnW = g_qp[6], sW = g_qp[7];
    float rowv = 0.f;
    #pragma unroll
    for (int rr = 0; rr < 3; rr++) rowv += ((unsigned)(h + rr - 1) < 28u) ? 1.f : 0.f;
    float SS = sA2 * sW;
    float base_out = (float)((size_t)0);
    (void)base_out;
    #pragma unroll
    for (int ti = 0; ti < 2; ti++){
        #pragma unroll
        for (int hh = 0; hh < 2; hh++){
            int px = ti*16 + hh*8 + g;
            if (px < 28){
                float colv = (px == 0 || px == 27) ? 2.f : 3.f;
                float nv   = rowv * colv * 128.0f;
                float rp   = rsum_p[px];
                #pragma unroll
                for (int e = 0; e < 2; e++){
                    int co = wid*8 + 2*tg + e;
                    float wvv = (px == 0) ? wvL[co] : ((px == 27) ? wvR[co] : wvM[co]);
                    float o = __fmaf_rn(SS, (float)acc[ti][hh*2+e],
                              __fmaf_rn(sA2*mnW, rp,
                              __fmaf_rn(mnA2*sW, wvv, mnA2*mnW*nv)));
                    out[((size_t)n*32 + co)*HW + h*28 + px] = o;
                }
            }
        }
    }
}

extern "C" void kernel_launch(void* const* d_in, const int* in_sizes, int n_in,
                              void* d_out, int out_size){
    const float* x  = (const float*)d_in[0];
    const float* g1 = (const float*)d_in[1];
    const float* b1 = (const float*)d_in[2];
    const float* m1 = (const float*)d_in[3];
    const float* v1 = (const float*)d_in[4];
    const float* w1 = (const float*)d_in[5];
    const float* g2 = (const float*)d_in[6];
    const float* b2 = (const float*)d_in[7];
    const float* m2 = (const float*)d_in[8];
    const float* v2 = (const float*)d_in[9];
    const float* w2 = (const float*)d_in[10];
    float* out = (float*)d_out;

    cudaFuncSetAttribute(k_conv1, cudaFuncAttributeMaxDynamicSharedMemorySize, DYN_SMEM);

    k_mm   <<<1040, 256>>>(x, g1, b1, m1, v1, w1, w2);
    k_prep <<<161, 256>>>(w1, w2);
    k_conv1<<<784, 256, DYN_SMEM>>>(x, g1, b1, m1, v1, g2, b2, m2, v2);
    k_qa2  <<<6272, 256>>>();
    k_conv2<<<1792, 128>>>(out);
}